// round 1
// baseline (speedup 1.0000x reference)
#include <cuda_runtime.h>
#include <math.h>

#define BB 2
#define SS 2048
#define DD 2048
#define HH 16
#define HKV 4
#define DH 128

// ---------------- scratch (static device globals; no allocation) ----------------
__device__ float g_Q[BB*HH*SS*DH];     // [B,H,S,DH]   32 MB
__device__ float g_K[BB*HKV*SS*DH];    // [B,HKV,S,DH]  8 MB
__device__ float g_V[BB*HKV*SS*DH];    //               8 MB
__device__ float g_AO[BB*SS*HH*DH];    // [B,S,H*DH]   32 MB
__device__ float g_cos[SS*(DH/2)];
__device__ float g_sin[SS*(DH/2)];

// ---------------- RoPE tables (double sincos of fp32-rounded angles) -------------
__global__ void rope_tables_kernel() {
    int i = blockIdx.x*blockDim.x + threadIdx.x;
    if (i >= SS*(DH/2)) return;
    int t = i / (DH/2);
    int f = i % (DH/2);
    // mimic jax fp32: inv_freq computed, rounded to fp32; angle = fp32(t)*fp32(inv)
    float invf = (float)exp(-((double)(2*f)/(double)DH) * log(10000.0));
    float ang  = (float)t * invf;
    g_cos[i] = (float)cos((double)ang);
    g_sin[i] = (float)sin((double)ang);
}

// ---------------- RoPE apply ----------------
__global__ void rope_q_kernel(const int* __restrict__ pos_ids) {
    int i = blockIdx.x*blockDim.x + threadIdx.x;       // b(1) h(4) s(11) d(6)
    if (i >= BB*HH*SS*64) return;
    int d = i & 63;
    int s = (i >> 6) & 2047;
    int h = (i >> 17) & 15;
    int b = i >> 21;
    int pos = pos_ids[b*SS + s];
    float c  = g_cos[pos*64 + d];
    float sn = g_sin[pos*64 + d];
    size_t base = (((size_t)b*HH + h)*SS + s)*DH;
    float x1 = g_Q[base + d], x2 = g_Q[base + d + 64];
    g_Q[base + d]      = x1*c - x2*sn;
    g_Q[base + d + 64] = x2*c + x1*sn;
}

__global__ void rope_k_kernel(const int* __restrict__ pos_ids) {
    int i = blockIdx.x*blockDim.x + threadIdx.x;       // b(1) h(2) s(11) d(6)
    if (i >= BB*HKV*SS*64) return;
    int d = i & 63;
    int s = (i >> 6) & 2047;
    int h = (i >> 17) & 3;
    int b = i >> 19;
    int pos = pos_ids[b*SS + s];
    float c  = g_cos[pos*64 + d];
    float sn = g_sin[pos*64 + d];
    size_t base = (((size_t)b*HKV + h)*SS + s)*DH;
    float x1 = g_K[base + d], x2 = g_K[base + d + 64];
    g_K[base + d]      = x1*c - x2*sn;
    g_K[base + d + 64] = x2*c + x1*sn;
}

// ---------------- fused QKV projection GEMM ----------------
// C[4096,3072] = X[4096,2048] @ [Wq | Wk | Wv]; epilogue scatters into g_Q/g_K/g_V
__global__ __launch_bounds__(256) void gemm_qkv_kernel(
    const float* __restrict__ X, const float* __restrict__ Wq,
    const float* __restrict__ Wk, const float* __restrict__ Wv)
{
    __shared__ float As[16][128];   // As[k][m]
    __shared__ float Bs[16][128];   // Bs[k][n]

    const int bm = blockIdx.y * 128;
    const int bn = blockIdx.x * 128;

    const float* W; int ncols, nloc, region;
    if (bn < 2048)      { W = Wq; ncols = 2048; nloc = bn;        region = 0; }
    else if (bn < 2560) { W = Wk; ncols = 512;  nloc = bn - 2048; region = 1; }
    else                { W = Wv; ncols = 512;  nloc = bn - 2560; region = 2; }

    const int tid = threadIdx.x;
    const int ty = tid >> 4, tx = tid & 15;

    float acc[8][8];
#pragma unroll
    for (int i = 0; i < 8; i++)
#pragma unroll
        for (int j = 0; j < 8; j++) acc[i][j] = 0.f;

    const int am  = tid >> 1;         // 0..127
    const int ak  = (tid & 1) * 8;    // 0 or 8
    const int bk  = tid >> 4;         // 0..15
    const int bn0 = (tid & 15) * 8;   // 0..120

    for (int k0 = 0; k0 < DD; k0 += 16) {
        const float* ap = X + (size_t)(bm + am) * DD + k0 + ak;
        float4 av0 = *(const float4*)ap;
        float4 av1 = *(const float4*)(ap + 4);
        As[ak+0][am] = av0.x; As[ak+1][am] = av0.y; As[ak+2][am] = av0.z; As[ak+3][am] = av0.w;
        As[ak+4][am] = av1.x; As[ak+5][am] = av1.y; As[ak+6][am] = av1.z; As[ak+7][am] = av1.w;

        const float* bp = W + (size_t)(k0 + bk) * ncols + nloc + bn0;
        *(float4*)&Bs[bk][bn0]     = *(const float4*)bp;
        *(float4*)&Bs[bk][bn0 + 4] = *(const float4*)(bp + 4);
        __syncthreads();

#pragma unroll
        for (int kk = 0; kk < 16; kk++) {
            float a[8], b[8];
            *(float4*)&a[0] = *(float4*)&As[kk][ty*8];
            *(float4*)&a[4] = *(float4*)&As[kk][ty*8 + 4];
            *(float4*)&b[0] = *(float4*)&Bs[kk][tx*4];
            *(float4*)&b[4] = *(float4*)&Bs[kk][64 + tx*4];
#pragma unroll
            for (int i = 0; i < 8; i++)
#pragma unroll
                for (int j = 0; j < 8; j++)
                    acc[i][j] += a[i] * b[j];
        }
        __syncthreads();
    }

    // epilogue: one head per 128-col block
    const int h = nloc >> 7;
#pragma unroll
    for (int i = 0; i < 8; i++) {
        int row = bm + ty*8 + i;
        int b = row >> 11, s = row & 2047;
        float* dst;
        if (region == 0)      dst = g_Q + (((size_t)b*HH  + h)*SS + s)*DH;
        else if (region == 1) dst = g_K + (((size_t)b*HKV + h)*SS + s)*DH;
        else                  dst = g_V + (((size_t)b*HKV + h)*SS + s)*DH;
        float4 v0 = {acc[i][0], acc[i][1], acc[i][2], acc[i][3]};
        float4 v1 = {acc[i][4], acc[i][5], acc[i][6], acc[i][7]};
        *(float4*)&dst[tx*4]      = v0;
        *(float4*)&dst[64 + tx*4] = v1;
    }
}

// ---------------- output projection GEMM ----------------
// out[4096,2048] = g_AO[4096,2048] @ Wo[2048,2048]
__global__ __launch_bounds__(256) void gemm_out_kernel(
    const float* __restrict__ Wo, float* __restrict__ Cout)
{
    __shared__ float As[16][128];
    __shared__ float Bs[16][128];

    const int bm = blockIdx.y * 128;
    const int bn = blockIdx.x * 128;
    const int tid = threadIdx.x;
    const int ty = tid >> 4, tx = tid & 15;

    float acc[8][8];
#pragma unroll
    for (int i = 0; i < 8; i++)
#pragma unroll
        for (int j = 0; j < 8; j++) acc[i][j] = 0.f;

    const int am  = tid >> 1;
    const int ak  = (tid & 1) * 8;
    const int bk  = tid >> 4;
    const int bn0 = (tid & 15) * 8;

    for (int k0 = 0; k0 < 2048; k0 += 16) {
        const float* ap = g_AO + (size_t)(bm + am) * 2048 + k0 + ak;
        float4 av0 = *(const float4*)ap;
        float4 av1 = *(const float4*)(ap + 4);
        As[ak+0][am] = av0.x; As[ak+1][am] = av0.y; As[ak+2][am] = av0.z; As[ak+3][am] = av0.w;
        As[ak+4][am] = av1.x; As[ak+5][am] = av1.y; As[ak+6][am] = av1.z; As[ak+7][am] = av1.w;

        const float* bp = Wo + (size_t)(k0 + bk) * 2048 + bn + bn0;
        *(float4*)&Bs[bk][bn0]     = *(const float4*)bp;
        *(float4*)&Bs[bk][bn0 + 4] = *(const float4*)(bp + 4);
        __syncthreads();

#pragma unroll
        for (int kk = 0; kk < 16; kk++) {
            float a[8], b[8];
            *(float4*)&a[0] = *(float4*)&As[kk][ty*8];
            *(float4*)&a[4] = *(float4*)&As[kk][ty*8 + 4];
            *(float4*)&b[0] = *(float4*)&Bs[kk][tx*4];
            *(float4*)&b[4] = *(float4*)&Bs[kk][64 + tx*4];
#pragma unroll
            for (int i = 0; i < 8; i++)
#pragma unroll
                for (int j = 0; j < 8; j++)
                    acc[i][j] += a[i] * b[j];
        }
        __syncthreads();
    }

#pragma unroll
    for (int i = 0; i < 8; i++) {
        int row = bm + ty*8 + i;
        float* dst = Cout + (size_t)row * 2048 + bn;
        float4 v0 = {acc[i][0], acc[i][1], acc[i][2], acc[i][3]};
        float4 v1 = {acc[i][4], acc[i][5], acc[i][6], acc[i][7]};
        *(float4*)&dst[tx*4]      = v0;
        *(float4*)&dst[64 + tx*4] = v1;
    }
}

// ---------------- flash attention (fp32, causal, GQA) ----------------
// grid: (qt=32, bh=32); 256 threads; 64x64 tiles, online softmax
// smem: Qs[64][128], KV[64][132] (shared K then V), Ssm[64][65], stats
#define FA_SMEM_FLOATS (64*128 + 64*132 + 64*65 + 3*64)

__global__ __launch_bounds__(256) void fa_kernel() {
    extern __shared__ float sm[];
    float* Qs   = sm;                    // 64*128
    float* KV   = Qs + 64*128;           // 64*132 (pad 4)
    float* Ssm  = KV + 64*132;           // 64*65
    float* mrow = Ssm + 64*65;
    float* lrow = mrow + 64;
    float* arow = lrow + 64;

    const int qt = blockIdx.x;
    const int bh = blockIdx.y;
    const int b  = bh >> 4, h = bh & 15, hk = h >> 2;
    const int tid = threadIdx.x;
    const int ty = tid >> 4, tx = tid & 15;

    const float scale = 0.08838834764831845f; // 1/sqrt(128)

    const float* Qg = g_Q + (((size_t)b*HH  + h )*SS + (size_t)qt*64)*DH;
    const float* Kg = g_K + (((size_t)b*HKV + hk)*SS)*DH;
    const float* Vg = g_V + (((size_t)b*HKV + hk)*SS)*DH;

    // load Q tile (scaled), float4
    for (int i4 = tid; i4 < 64*32; i4 += 256) {
        int r = i4 >> 5, c4 = (i4 & 31) * 4;
        float4 q = *(const float4*)&Qg[r*DH + c4];
        q.x *= scale; q.y *= scale; q.z *= scale; q.w *= scale;
        *(float4*)&Qs[r*128 + c4] = q;
    }
    if (tid < 64) { mrow[tid] = -1e30f; lrow[tid] = 0.f; }

    float oacc[4][8];
#pragma unroll
    for (int i = 0; i < 4; i++)
#pragma unroll
        for (int j = 0; j < 8; j++) oacc[i][j] = 0.f;

    for (int kt = 0; kt <= qt; kt++) {
        __syncthreads();  // protect Qs (first iter) / KV,Ssm reuse
        {   // load K tile
            const float* kg = Kg + (size_t)kt*64*DH;
            for (int i4 = tid; i4 < 64*32; i4 += 256) {
                int r = i4 >> 5, c4 = (i4 & 31) * 4;
                *(float4*)&KV[r*132 + c4] = *(const float4*)&kg[r*DH + c4];
            }
        }
        __syncthreads();

        // scores: S[64][64], 4x4 per thread (cols strided: tx + 16j)
        float acc[4][4];
#pragma unroll
        for (int i = 0; i < 4; i++)
#pragma unroll
            for (int j = 0; j < 4; j++) acc[i][j] = 0.f;

#pragma unroll 4
        for (int d = 0; d < 128; d += 4) {
            float4 a[4], kb[4];
#pragma unroll
            for (int i = 0; i < 4; i++) a[i]  = *(float4*)&Qs[(ty*4+i)*128 + d];
#pragma unroll
            for (int j = 0; j < 4; j++) kb[j] = *(float4*)&KV[(tx + 16*j)*132 + d];
#pragma unroll
            for (int i = 0; i < 4; i++)
#pragma unroll
                for (int j = 0; j < 4; j++)
                    acc[i][j] += a[i].x*kb[j].x + a[i].y*kb[j].y
                               + a[i].z*kb[j].z + a[i].w*kb[j].w;
        }

        const bool diag = (kt == qt);
#pragma unroll
        for (int i = 0; i < 4; i++) {
            int r = ty*4 + i;
#pragma unroll
            for (int j = 0; j < 4; j++) {
                int c = tx + 16*j;
                float v = acc[i][j];
                if (diag && c > r) v = -1e9f;
                Ssm[r*65 + c] = v;
            }
        }
        __syncthreads();

        // load V tile into same buffer; threads 0..63 also do row softmax
        {
            const float* vg = Vg + (size_t)kt*64*DH;
            for (int i4 = tid; i4 < 64*32; i4 += 256) {
                int r = i4 >> 5, c4 = (i4 & 31) * 4;
                *(float4*)&KV[r*132 + c4] = *(const float4*)&vg[r*DH + c4];
            }
        }
        if (tid < 64) {
            int r = tid;
            float mold = mrow[r];
            float tmax = mold;
#pragma unroll 8
            for (int c = 0; c < 64; c++) tmax = fmaxf(tmax, Ssm[r*65 + c]);
            float sum = 0.f;
#pragma unroll 8
            for (int c = 0; c < 64; c++) {
                float p = __expf(Ssm[r*65 + c] - tmax);
                Ssm[r*65 + c] = p;
                sum += p;
            }
            float al = __expf(mold - tmax);
            arow[r] = al;
            lrow[r] = lrow[r]*al + sum;
            mrow[r] = tmax;
        }
        __syncthreads();

        // rescale + PV
        float al[4];
#pragma unroll
        for (int i = 0; i < 4; i++) al[i] = arow[ty*4 + i];
#pragma unroll
        for (int i = 0; i < 4; i++)
#pragma unroll
            for (int j = 0; j < 8; j++) oacc[i][j] *= al[i];

#pragma unroll 4
        for (int kk = 0; kk < 64; kk++) {
            float p[4];
#pragma unroll
            for (int i = 0; i < 4; i++) p[i] = Ssm[(ty*4+i)*65 + kk];
            float4 v0 = *(float4*)&KV[kk*132 + tx*4];
            float4 v1 = *(float4*)&KV[kk*132 + 64 + tx*4];
#pragma unroll
            for (int i = 0; i < 4; i++) {
                oacc[i][0] += p[i]*v0.x; oacc[i][1] += p[i]*v0.y;
                oacc[i][2] += p[i]*v0.z; oacc[i][3] += p[i]*v0.w;
                oacc[i][4] += p[i]*v1.x; oacc[i][5] += p[i]*v1.y;
                oacc[i][6] += p[i]*v1.z; oacc[i][7] += p[i]*v1.w;
            }
        }
    }

    // finalize: O /= l ; write AO[b, s, h*128 + d]
#pragma unroll
    for (int i = 0; i < 4; i++) {
        int r = ty*4 + i;
        float inv = 1.f / lrow[r];
        int sglob = qt*64 + r;
        float* dst = g_AO + ((size_t)b*SS + sglob)*(HH*DH) + h*DH;
        float4 o0 = {oacc[i][0]*inv, oacc[i][1]*inv, oacc[i][2]*inv, oacc[i][3]*inv};
        float4 o1 = {oacc[i][4]*inv, oacc[i][5]*inv, oacc[i][6]*inv, oacc[i][7]*inv};
        *(float4*)&dst[tx*4]      = o0;
        *(float4*)&dst[64 + tx*4] = o1;
    }
}

// ---------------- launcher ----------------
extern "C" void kernel_launch(void* const* d_in, const int* in_sizes, int n_in,
                              void* d_out, int out_size) {
    (void)in_sizes; (void)n_in; (void)out_size;
    const float* X   = (const float*)d_in[0];
    const int*   pos = (const int*)  d_in[1];
    const float* wq  = (const float*)d_in[2];
    const float* wk  = (const float*)d_in[3];
    const float* wv  = (const float*)d_in[4];
    const float* wo  = (const float*)d_in[5];
    float* out = (float*)d_out;

    rope_tables_kernel<<<(SS*(DH/2) + 255)/256, 256>>>();
    gemm_qkv_kernel<<<dim3(24, 32), 256>>>(X, wq, wk, wv);
    rope_q_kernel<<<(BB*HH*SS*64)/256, 256>>>(pos);
    rope_k_kernel<<<(BB*HKV*SS*64)/256, 256>>>(pos);

    const int fa_smem = FA_SMEM_FLOATS * 4;
    cudaFuncSetAttribute(fa_kernel, cudaFuncAttributeMaxDynamicSharedMemorySize, fa_smem);
    fa_kernel<<<dim3(32, 32), 256, fa_smem>>>();

    gemm_out_kernel<<<dim3(16, 32), 256>>>(wo, out);
}

// round 2
// speedup vs baseline: 1.4892x; 1.4892x over previous
#include <cuda_runtime.h>
#include <math.h>
#include <stdint.h>

#define BB 2
#define SS 2048
#define DD 2048
#define HH 16
#define HKV 4
#define DH 128

// ---------------- scratch (static device globals; no allocation) ----------------
__device__ float g_Q[BB*HH*SS*DH];     // [B,H,S,DH]   32 MB
__device__ float g_K[BB*HKV*SS*DH];    // [B,HKV,S,DH]  8 MB
__device__ float g_V[BB*HKV*SS*DH];    //               8 MB
__device__ float g_AO[BB*SS*HH*DH];    // [B,S,H*DH]   32 MB
__device__ float g_cos[SS*(DH/2)];
__device__ float g_sin[SS*(DH/2)];

// ---------------- helpers ----------------
__device__ __forceinline__ uint32_t f2tf32(float x) {
    uint32_t r;
    asm("cvt.rna.tf32.f32 %0, %1;" : "=r"(r) : "f"(x));
    return r;
}

__device__ __forceinline__ void mma_tf32(float* c, const uint32_t* a, const uint32_t* b) {
    asm volatile(
        "mma.sync.aligned.m16n8k8.row.col.f32.tf32.tf32.f32 "
        "{%0,%1,%2,%3}, {%4,%5,%6,%7}, {%8,%9}, {%0,%1,%2,%3};\n"
        : "+f"(c[0]), "+f"(c[1]), "+f"(c[2]), "+f"(c[3])
        : "r"(a[0]), "r"(a[1]), "r"(a[2]), "r"(a[3]), "r"(b[0]), "r"(b[1]));
}

// ---------------- RoPE tables ----------------
__global__ void rope_tables_kernel() {
    int i = blockIdx.x*blockDim.x + threadIdx.x;
    if (i >= SS*(DH/2)) return;
    int t = i / (DH/2);
    int f = i % (DH/2);
    float invf = (float)exp(-((double)(2*f)/(double)DH) * log(10000.0));
    float ang  = (float)t * invf;
    g_cos[i] = (float)cos((double)ang);
    g_sin[i] = (float)sin((double)ang);
}

// ---------------- RoPE apply ----------------
__global__ void rope_q_kernel(const int* __restrict__ pos_ids) {
    int i = blockIdx.x*blockDim.x + threadIdx.x;
    if (i >= BB*HH*SS*64) return;
    int d = i & 63;
    int s = (i >> 6) & 2047;
    int h = (i >> 17) & 15;
    int b = i >> 21;
    int pos = pos_ids[b*SS + s];
    float c  = g_cos[pos*64 + d];
    float sn = g_sin[pos*64 + d];
    size_t base = (((size_t)b*HH + h)*SS + s)*DH;
    float x1 = g_Q[base + d], x2 = g_Q[base + d + 64];
    g_Q[base + d]      = x1*c - x2*sn;
    g_Q[base + d + 64] = x2*c + x1*sn;
}

__global__ void rope_k_kernel(const int* __restrict__ pos_ids) {
    int i = blockIdx.x*blockDim.x + threadIdx.x;
    if (i >= BB*HKV*SS*64) return;
    int d = i & 63;
    int s = (i >> 6) & 2047;
    int h = (i >> 17) & 3;
    int b = i >> 19;
    int pos = pos_ids[b*SS + s];
    float c  = g_cos[pos*64 + d];
    float sn = g_sin[pos*64 + d];
    size_t base = (((size_t)b*HKV + h)*SS + s)*DH;
    float x1 = g_K[base + d], x2 = g_K[base + d + 64];
    g_K[base + d]      = x1*c - x2*sn;
    g_K[base + d + 64] = x2*c + x1*sn;
}

// ================= TF32 tensor-core GEMM (shared structure) =================
// Block tile 128x128, BK=32, 8 warps (4 along M x 2 along N), warp tile 32x64.
// Smem stride 136 words -> all fragment LDS conflict-free.
#define SA 136

// ---------------- fused QKV projection ----------------
__global__ __launch_bounds__(256) void gemm_qkv_tc(
    const float* __restrict__ X, const float* __restrict__ Wq,
    const float* __restrict__ Wk, const float* __restrict__ Wv)
{
    __shared__ uint32_t As[32*SA];
    __shared__ uint32_t Bs[32*SA];

    const int bm = blockIdx.y * 128;
    const int bn = blockIdx.x * 128;

    const float* W; int ncols, nloc, region;
    if (bn < 2048)      { W = Wq; ncols = 2048; nloc = bn;        region = 0; }
    else if (bn < 2560) { W = Wk; ncols = 512;  nloc = bn - 2048; region = 1; }
    else                { W = Wv; ncols = 512;  nloc = bn - 2560; region = 2; }

    const int tid  = threadIdx.x;
    const int lane = tid & 31;
    const int wid  = tid >> 5;
    const int gid  = lane >> 2;   // 0..7
    const int tig  = lane & 3;    // 0..3
    const int wm   = wid & 3;     // 0..3
    const int wn   = wid >> 2;    // 0..1

    float acc[2][8][4];
#pragma unroll
    for (int mt = 0; mt < 2; mt++)
#pragma unroll
        for (int nt = 0; nt < 8; nt++)
#pragma unroll
            for (int j = 0; j < 4; j++) acc[mt][nt][j] = 0.f;

    const int am  = tid & 127;
    const int akh = (tid >> 7) * 16;
    const int bc4 = (tid & 31) * 4;
    const int br  = tid >> 5;

    for (int k0 = 0; k0 < DD; k0 += 32) {
        // A -> As[k][m] (transposed, tf32)
        const float* ap = X + (size_t)(bm + am) * DD + k0 + akh;
#pragma unroll
        for (int e = 0; e < 4; e++) {
            float4 v = *(const float4*)(ap + 4*e);
            As[(akh + 4*e + 0)*SA + am] = f2tf32(v.x);
            As[(akh + 4*e + 1)*SA + am] = f2tf32(v.y);
            As[(akh + 4*e + 2)*SA + am] = f2tf32(v.z);
            As[(akh + 4*e + 3)*SA + am] = f2tf32(v.w);
        }
        // B -> Bs[k][n] (tf32)
#pragma unroll
        for (int i = 0; i < 4; i++) {
            const float* bp = W + (size_t)(k0 + br + 8*i) * ncols + nloc + bc4;
            float4 v = *(const float4*)bp;
            uint32_t* d = &Bs[(br + 8*i)*SA + bc4];
            d[0] = f2tf32(v.x); d[1] = f2tf32(v.y);
            d[2] = f2tf32(v.z); d[3] = f2tf32(v.w);
        }
        __syncthreads();

#pragma unroll
        for (int ks = 0; ks < 4; ks++) {
            const int k8 = ks * 8;
            uint32_t a[2][4], b[8][2];
#pragma unroll
            for (int mt = 0; mt < 2; mt++) {
                int m0 = wm*32 + mt*16;
                a[mt][0] = As[(k8 + tig    )*SA + m0 + gid];
                a[mt][1] = As[(k8 + tig    )*SA + m0 + gid + 8];
                a[mt][2] = As[(k8 + tig + 4)*SA + m0 + gid];
                a[mt][3] = As[(k8 + tig + 4)*SA + m0 + gid + 8];
            }
#pragma unroll
            for (int nt = 0; nt < 8; nt++) {
                int n0 = wn*64 + nt*8;
                b[nt][0] = Bs[(k8 + tig    )*SA + n0 + gid];
                b[nt][1] = Bs[(k8 + tig + 4)*SA + n0 + gid];
            }
#pragma unroll
            for (int mt = 0; mt < 2; mt++)
#pragma unroll
                for (int nt = 0; nt < 8; nt++)
                    mma_tf32(acc[mt][nt], a[mt], b[nt]);
        }
        __syncthreads();
    }

    // epilogue: scatter to g_Q / g_K / g_V
    const int h = nloc >> 7;
#pragma unroll
    for (int mt = 0; mt < 2; mt++) {
        int row = bm + wm*32 + mt*16 + gid;
        int b_ = row >> 11, s = row & 2047;
        float* base;
        if (region == 0)      base = g_Q + (((size_t)b_*HH  + h)*SS + s)*DH;
        else if (region == 1) base = g_K + (((size_t)b_*HKV + h)*SS + s)*DH;
        else                  base = g_V + (((size_t)b_*HKV + h)*SS + s)*DH;
        float* base8 = base + 8*DH;  // row+8 stays in same (b, head) region
#pragma unroll
        for (int nt = 0; nt < 8; nt++) {
            int col = wn*64 + nt*8 + 2*tig;
            float2 v0 = {acc[mt][nt][0], acc[mt][nt][1]};
            float2 v1 = {acc[mt][nt][2], acc[mt][nt][3]};
            *(float2*)&base [col] = v0;
            *(float2*)&base8[col] = v1;
        }
    }
}

// ---------------- output projection ----------------
__global__ __launch_bounds__(256) void gemm_out_tc(
    const float* __restrict__ Wo, float* __restrict__ Cout)
{
    __shared__ uint32_t As[32*SA];
    __shared__ uint32_t Bs[32*SA];

    const int bm = blockIdx.y * 128;
    const int bn = blockIdx.x * 128;

    const int tid  = threadIdx.x;
    const int lane = tid & 31;
    const int wid  = tid >> 5;
    const int gid  = lane >> 2;
    const int tig  = lane & 3;
    const int wm   = wid & 3;
    const int wn   = wid >> 2;

    float acc[2][8][4];
#pragma unroll
    for (int mt = 0; mt < 2; mt++)
#pragma unroll
        for (int nt = 0; nt < 8; nt++)
#pragma unroll
            for (int j = 0; j < 4; j++) acc[mt][nt][j] = 0.f;

    const int am  = tid & 127;
    const int akh = (tid >> 7) * 16;
    const int bc4 = (tid & 31) * 4;
    const int br  = tid >> 5;

    for (int k0 = 0; k0 < 2048; k0 += 32) {
        const float* ap = g_AO + (size_t)(bm + am) * 2048 + k0 + akh;
#pragma unroll
        for (int e = 0; e < 4; e++) {
            float4 v = *(const float4*)(ap + 4*e);
            As[(akh + 4*e + 0)*SA + am] = f2tf32(v.x);
            As[(akh + 4*e + 1)*SA + am] = f2tf32(v.y);
            As[(akh + 4*e + 2)*SA + am] = f2tf32(v.z);
            As[(akh + 4*e + 3)*SA + am] = f2tf32(v.w);
        }
#pragma unroll
        for (int i = 0; i < 4; i++) {
            const float* bp = Wo + (size_t)(k0 + br + 8*i) * 2048 + bn + bc4;
            float4 v = *(const float4*)bp;
            uint32_t* d = &Bs[(br + 8*i)*SA + bc4];
            d[0] = f2tf32(v.x); d[1] = f2tf32(v.y);
            d[2] = f2tf32(v.z); d[3] = f2tf32(v.w);
        }
        __syncthreads();

#pragma unroll
        for (int ks = 0; ks < 4; ks++) {
            const int k8 = ks * 8;
            uint32_t a[2][4], b[8][2];
#pragma unroll
            for (int mt = 0; mt < 2; mt++) {
                int m0 = wm*32 + mt*16;
                a[mt][0] = As[(k8 + tig    )*SA + m0 + gid];
                a[mt][1] = As[(k8 + tig    )*SA + m0 + gid + 8];
                a[mt][2] = As[(k8 + tig + 4)*SA + m0 + gid];
                a[mt][3] = As[(k8 + tig + 4)*SA + m0 + gid + 8];
            }
#pragma unroll
            for (int nt = 0; nt < 8; nt++) {
                int n0 = wn*64 + nt*8;
                b[nt][0] = Bs[(k8 + tig    )*SA + n0 + gid];
                b[nt][1] = Bs[(k8 + tig + 4)*SA + n0 + gid];
            }
#pragma unroll
            for (int mt = 0; mt < 2; mt++)
#pragma unroll
                for (int nt = 0; nt < 8; nt++)
                    mma_tf32(acc[mt][nt], a[mt], b[nt]);
        }
        __syncthreads();
    }

#pragma unroll
    for (int mt = 0; mt < 2; mt++) {
        int row = bm + wm*32 + mt*16 + gid;
        float* base  = Cout + (size_t)row * 2048 + bn;
        float* base8 = base + 8 * 2048;
#pragma unroll
        for (int nt = 0; nt < 8; nt++) {
            int col = wn*64 + nt*8 + 2*tig;
            float2 v0 = {acc[mt][nt][0], acc[mt][nt][1]};
            float2 v1 = {acc[mt][nt][2], acc[mt][nt][3]};
            *(float2*)&base [col] = v0;
            *(float2*)&base8[col] = v1;
        }
    }
}

// ---------------- flash attention (fp32, causal, GQA) ----------------
#define FA_SMEM_FLOATS (64*128 + 64*132 + 64*65 + 3*64)

__global__ __launch_bounds__(256) void fa_kernel() {
    extern __shared__ float sm[];
    float* Qs   = sm;
    float* KV   = Qs + 64*128;
    float* Ssm  = KV + 64*132;
    float* mrow = Ssm + 64*65;
    float* lrow = mrow + 64;
    float* arow = lrow + 64;

    const int qt = blockIdx.x;
    const int bh = blockIdx.y;
    const int b  = bh >> 4, h = bh & 15, hk = h >> 2;
    const int tid = threadIdx.x;
    const int ty = tid >> 4, tx = tid & 15;

    const float scale = 0.08838834764831845f;

    const float* Qg = g_Q + (((size_t)b*HH  + h )*SS + (size_t)qt*64)*DH;
    const float* Kg = g_K + (((size_t)b*HKV + hk)*SS)*DH;
    const float* Vg = g_V + (((size_t)b*HKV + hk)*SS)*DH;

    for (int i4 = tid; i4 < 64*32; i4 += 256) {
        int r = i4 >> 5, c4 = (i4 & 31) * 4;
        float4 q = *(const float4*)&Qg[r*DH + c4];
        q.x *= scale; q.y *= scale; q.z *= scale; q.w *= scale;
        *(float4*)&Qs[r*128 + c4] = q;
    }
    if (tid < 64) { mrow[tid] = -1e30f; lrow[tid] = 0.f; }

    float oacc[4][8];
#pragma unroll
    for (int i = 0; i < 4; i++)
#pragma unroll
        for (int j = 0; j < 8; j++) oacc[i][j] = 0.f;

    for (int kt = 0; kt <= qt; kt++) {
        __syncthreads();
        {
            const float* kg = Kg + (size_t)kt*64*DH;
            for (int i4 = tid; i4 < 64*32; i4 += 256) {
                int r = i4 >> 5, c4 = (i4 & 31) * 4;
                *(float4*)&KV[r*132 + c4] = *(const float4*)&kg[r*DH + c4];
            }
        }
        __syncthreads();

        float acc[4][4];
#pragma unroll
        for (int i = 0; i < 4; i++)
#pragma unroll
            for (int j = 0; j < 4; j++) acc[i][j] = 0.f;

#pragma unroll 4
        for (int d = 0; d < 128; d += 4) {
            float4 a[4], kb[4];
#pragma unroll
            for (int i = 0; i < 4; i++) a[i]  = *(float4*)&Qs[(ty*4+i)*128 + d];
#pragma unroll
            for (int j = 0; j < 4; j++) kb[j] = *(float4*)&KV[(tx + 16*j)*132 + d];
#pragma unroll
            for (int i = 0; i < 4; i++)
#pragma unroll
                for (int j = 0; j < 4; j++)
                    acc[i][j] += a[i].x*kb[j].x + a[i].y*kb[j].y
                               + a[i].z*kb[j].z + a[i].w*kb[j].w;
        }

        const bool diag = (kt == qt);
#pragma unroll
        for (int i = 0; i < 4; i++) {
            int r = ty*4 + i;
#pragma unroll
            for (int j = 0; j < 4; j++) {
                int c = tx + 16*j;
                float v = acc[i][j];
                if (diag && c > r) v = -1e9f;
                Ssm[r*65 + c] = v;
            }
        }
        __syncthreads();

        {
            const float* vg = Vg + (size_t)kt*64*DH;
            for (int i4 = tid; i4 < 64*32; i4 += 256) {
                int r = i4 >> 5, c4 = (i4 & 31) * 4;
                *(float4*)&KV[r*132 + c4] = *(const float4*)&vg[r*DH + c4];
            }
        }
        if (tid < 64) {
            int r = tid;
            float mold = mrow[r];
            float tmax = mold;
#pragma unroll 8
            for (int c = 0; c < 64; c++) tmax = fmaxf(tmax, Ssm[r*65 + c]);
            float sum = 0.f;
#pragma unroll 8
            for (int c = 0; c < 64; c++) {
                float p = __expf(Ssm[r*65 + c] - tmax);
                Ssm[r*65 + c] = p;
                sum += p;
            }
            float al = __expf(mold - tmax);
            arow[r] = al;
            lrow[r] = lrow[r]*al + sum;
            mrow[r] = tmax;
        }
        __syncthreads();

        float al[4];
#pragma unroll
        for (int i = 0; i < 4; i++) al[i] = arow[ty*4 + i];
#pragma unroll
        for (int i = 0; i < 4; i++)
#pragma unroll
            for (int j = 0; j < 8; j++) oacc[i][j] *= al[i];

#pragma unroll 4
        for (int kk = 0; kk < 64; kk++) {
            float p[4];
#pragma unroll
            for (int i = 0; i < 4; i++) p[i] = Ssm[(ty*4+i)*65 + kk];
            float4 v0 = *(float4*)&KV[kk*132 + tx*4];
            float4 v1 = *(float4*)&KV[kk*132 + 64 + tx*4];
#pragma unroll
            for (int i = 0; i < 4; i++) {
                oacc[i][0] += p[i]*v0.x; oacc[i][1] += p[i]*v0.y;
                oacc[i][2] += p[i]*v0.z; oacc[i][3] += p[i]*v0.w;
                oacc[i][4] += p[i]*v1.x; oacc[i][5] += p[i]*v1.y;
                oacc[i][6] += p[i]*v1.z; oacc[i][7] += p[i]*v1.w;
            }
        }
    }

#pragma unroll
    for (int i = 0; i < 4; i++) {
        int r = ty*4 + i;
        float inv = 1.f / lrow[r];
        int sglob = qt*64 + r;
        float* dst = g_AO + ((size_t)b*SS + sglob)*(HH*DH) + h*DH;
        float4 o0 = {oacc[i][0]*inv, oacc[i][1]*inv, oacc[i][2]*inv, oacc[i][3]*inv};
        float4 o1 = {oacc[i][4]*inv, oacc[i][5]*inv, oacc[i][6]*inv, oacc[i][7]*inv};
        *(float4*)&dst[tx*4]      = o0;
        *(float4*)&dst[64 + tx*4] = o1;
    }
}

// ---------------- launcher ----------------
extern "C" void kernel_launch(void* const* d_in, const int* in_sizes, int n_in,
                              void* d_out, int out_size) {
    (void)in_sizes; (void)n_in; (void)out_size;
    const float* X   = (const float*)d_in[0];
    const int*   pos = (const int*)  d_in[1];
    const float* wq  = (const float*)d_in[2];
    const float* wk  = (const float*)d_in[3];
    const float* wv  = (const float*)d_in[4];
    const float* wo  = (const float*)d_in[5];
    float* out = (float*)d_out;

    rope_tables_kernel<<<(SS*(DH/2) + 255)/256, 256>>>();
    gemm_qkv_tc<<<dim3(24, 32), 256>>>(X, wq, wk, wv);
    rope_q_kernel<<<(BB*HH*SS*64)/256, 256>>>(pos);
    rope_k_kernel<<<(BB*HKV*SS*64)/256, 256>>>(pos);

    const int fa_smem = FA_SMEM_FLOATS * 4;
    cudaFuncSetAttribute(fa_kernel, cudaFuncAttributeMaxDynamicSharedMemorySize, fa_smem);
    fa_kernel<<<dim3(32, 32), 256, fa_smem>>>();

    gemm_out_tc<<<dim3(16, 32), 256>>>(wo, out);
}